// round 2
// baseline (speedup 1.0000x reference)
#include <cuda_runtime.h>
#include <math.h>

// Problem constants
#define S_LEN 16384
#define E_DIM 2048
#define H_DIM 1024
#define C_CLS 5
#define NCHUNK 256                        // row chunks for column-sum phase 1
#define ROWS_PER_CHUNK (S_LEN / NCHUNK)   // 64

// Scratch (device allocation is forbidden -> __device__ globals)
__device__ float g_part[NCHUNK * E_DIM];  // 2 MB partial column sums
__device__ float g_x[E_DIM];              // attn_applied == column sum
__device__ float g_h1[H_DIM];
__device__ float g_h2[H_DIM];

__device__ __forceinline__ float dot4(float4 a, float4 b) {
    return a.x * b.x + a.y * b.y + a.z * b.z + a.w * b.w;
}
__device__ __forceinline__ float sigf(float v) {
    return 1.0f / (1.0f + __expf(-v));
}

// ---------------------------------------------------------------------------
// Kernel 1: partial column sums of encoder_hiddens (S x E), B=1.
// grid = (E/1024, NCHUNK), block = 256. Each thread sums one float4 column
// group over ROWS_PER_CHUNK rows. Fully coalesced 16B loads, 8 independent
// loads in flight per thread (unroll 8).
// ---------------------------------------------------------------------------
__global__ void __launch_bounds__(256) colsum_partial(const float* __restrict__ enc) {
    const int c4 = blockIdx.x * 256 + threadIdx.x;   // float4 column index [0, 512)
    const float4* __restrict__ e4 = (const float4*)enc;
    const size_t row0 = (size_t)blockIdx.y * ROWS_PER_CHUNK;
    float4 s = make_float4(0.f, 0.f, 0.f, 0.f);
#pragma unroll 8
    for (int r = 0; r < ROWS_PER_CHUNK; r++) {
        float4 v = e4[(row0 + r) * (E_DIM / 4) + c4];
        s.x += v.x; s.y += v.y; s.z += v.z; s.w += v.w;
    }
    ((float4*)g_part)[(size_t)blockIdx.y * (E_DIM / 4) + c4] = s;
}

// ---------------------------------------------------------------------------
// Kernel 2: reduce the NCHUNK partials per column -> g_x. Deterministic
// (fixed summation order; no float atomics, so timed replays are bit-stable).
// ---------------------------------------------------------------------------
__global__ void __launch_bounds__(256) colsum_reduce() {
    const int e = blockIdx.x * blockDim.x + threadIdx.x;  // [0, 2048)
    float s = 0.f;
#pragma unroll 8
    for (int c = 0; c < NCHUNK; c++) s += g_part[c * E_DIM + e];
    g_x[e] = s;
}

// ---------------------------------------------------------------------------
// LSTM cell: one block per hidden unit j. The block streams the 4 gate weight
// rows (i,f,g,o) for both w_ih (IN cols) and w_hh (H cols); the activation
// vectors are tiny (L2/L1 resident after the first blocks touch them).
// Block-reduce, thread 0 applies the gate nonlinearity.
// ---------------------------------------------------------------------------
template <int IN, int BLK>
__global__ void __launch_bounds__(BLK) lstm_cell(const float* __restrict__ xin,
                          const float* __restrict__ hprev,
                          const float* __restrict__ cprev,
                          const float* __restrict__ w_ih,
                          const float* __restrict__ w_hh,
                          const float* __restrict__ b_ih,
                          const float* __restrict__ b_hh,
                          float* __restrict__ hout) {
    const int j = blockIdx.x;  // hidden unit [0, H_DIM)
    float4 acc = make_float4(0.f, 0.f, 0.f, 0.f);  // gates i,f,g,o

    const float4* __restrict__ x4 = (const float4*)xin;
    const float4* __restrict__ h4 = (const float4*)hprev;
    const float4* __restrict__ wi0 = (const float4*)(w_ih + (size_t)(0 * H_DIM + j) * IN);
    const float4* __restrict__ wi1 = (const float4*)(w_ih + (size_t)(1 * H_DIM + j) * IN);
    const float4* __restrict__ wi2 = (const float4*)(w_ih + (size_t)(2 * H_DIM + j) * IN);
    const float4* __restrict__ wi3 = (const float4*)(w_ih + (size_t)(3 * H_DIM + j) * IN);

#pragma unroll 2
    for (int t = threadIdx.x; t < IN / 4; t += BLK) {
        float4 xv = x4[t];
        acc.x += dot4(wi0[t], xv);
        acc.y += dot4(wi1[t], xv);
        acc.z += dot4(wi2[t], xv);
        acc.w += dot4(wi3[t], xv);
    }

    const float4* __restrict__ wh0 = (const float4*)(w_hh + (size_t)(0 * H_DIM + j) * H_DIM);
    const float4* __restrict__ wh1 = (const float4*)(w_hh + (size_t)(1 * H_DIM + j) * H_DIM);
    const float4* __restrict__ wh2 = (const float4*)(w_hh + (size_t)(2 * H_DIM + j) * H_DIM);
    const float4* __restrict__ wh3 = (const float4*)(w_hh + (size_t)(3 * H_DIM + j) * H_DIM);

#pragma unroll 2
    for (int t = threadIdx.x; t < H_DIM / 4; t += BLK) {
        float4 hv = h4[t];
        acc.x += dot4(wh0[t], hv);
        acc.y += dot4(wh1[t], hv);
        acc.z += dot4(wh2[t], hv);
        acc.w += dot4(wh3[t], hv);
    }

    // warp reduce each gate
#pragma unroll
    for (int o = 16; o; o >>= 1) {
        acc.x += __shfl_down_sync(0xffffffffu, acc.x, o);
        acc.y += __shfl_down_sync(0xffffffffu, acc.y, o);
        acc.z += __shfl_down_sync(0xffffffffu, acc.z, o);
        acc.w += __shfl_down_sync(0xffffffffu, acc.w, o);
    }
    __shared__ float4 sm[BLK / 32];
    const int lane = threadIdx.x & 31, warp = threadIdx.x >> 5;
    if (lane == 0) sm[warp] = acc;
    __syncthreads();
    if (threadIdx.x == 0) {
        float4 t = sm[0];
#pragma unroll
        for (int w = 1; w < BLK / 32; w++) {
            t.x += sm[w].x; t.y += sm[w].y; t.z += sm[w].z; t.w += sm[w].w;
        }
        float gi = t.x + b_ih[0 * H_DIM + j] + b_hh[0 * H_DIM + j];
        float gf = t.y + b_ih[1 * H_DIM + j] + b_hh[1 * H_DIM + j];
        float gg = t.z + b_ih[2 * H_DIM + j] + b_hh[2 * H_DIM + j];
        float go = t.w + b_ih[3 * H_DIM + j] + b_hh[3 * H_DIM + j];
        float c2 = sigf(gf) * cprev[j] + sigf(gi) * tanhf(gg);
        hout[j] = sigf(go) * tanhf(c2);
    }
}

// ---------------------------------------------------------------------------
// FC head: one block per class, dot(h2, fc_w[cls]) + b.
// ---------------------------------------------------------------------------
__global__ void __launch_bounds__(256) fc_kernel(const float* __restrict__ fc_w,
                          const float* __restrict__ fc_b,
                          float* __restrict__ out) {
    const int cls = blockIdx.x;
    const float4* __restrict__ h4 = (const float4*)g_h2;
    const float4* __restrict__ w4 = (const float4*)(fc_w + (size_t)cls * H_DIM);
    float s = 0.f;
    for (int t = threadIdx.x; t < H_DIM / 4; t += blockDim.x) s += dot4(w4[t], h4[t]);
#pragma unroll
    for (int o = 16; o; o >>= 1) s += __shfl_down_sync(0xffffffffu, s, o);
    __shared__ float sm[8];
    const int lane = threadIdx.x & 31, warp = threadIdx.x >> 5;
    if (lane == 0) sm[warp] = s;
    __syncthreads();
    if (threadIdx.x == 0) {
        float t = 0.f;
        const int nwarps = (int)(blockDim.x >> 5);
        for (int w = 0; w < nwarps; w++) t += sm[w];
        out[cls] = t + fc_b[cls];
    }
}

extern "C" void kernel_launch(void* const* d_in, const int* in_sizes, int n_in,
                              void* d_out, int out_size) {
    const float* enc     = (const float*)d_in[0];   // (S, 1, E)
    const float* hidden  = (const float*)d_in[1];   // (2, 1, H)
    const float* c_in    = (const float*)d_in[2];   // (2, 1, H)
    // d_in[3] attn_w, d_in[4] attn_b: mathematically dead — softmax over the
    // size-1 output axis is identically 1, so attn_applied is a plain column sum.
    const float* w_ih_l0 = (const float*)d_in[5];
    const float* w_hh_l0 = (const float*)d_in[6];
    const float* b_ih_l0 = (const float*)d_in[7];
    const float* b_hh_l0 = (const float*)d_in[8];
    const float* w_ih_l1 = (const float*)d_in[9];
    const float* w_hh_l1 = (const float*)d_in[10];
    const float* b_ih_l1 = (const float*)d_in[11];
    const float* b_hh_l1 = (const float*)d_in[12];
    const float* fc_w    = (const float*)d_in[13];
    const float* fc_b    = (const float*)d_in[14];
    float* out = (float*)d_out;

    float* x_dev;  cudaGetSymbolAddress((void**)&x_dev,  g_x);
    float* h1_dev; cudaGetSymbolAddress((void**)&h1_dev, g_h1);
    float* h2_dev; cudaGetSymbolAddress((void**)&h2_dev, g_h2);

    // 1) attn_applied = column sum of encoder_hiddens
    colsum_partial<<<dim3(E_DIM / 1024, NCHUNK), 256>>>(enc);
    colsum_reduce<<<E_DIM / 256, 256>>>();

    // 2) LSTM layer 0: x = colsum (E=2048), h = hidden[0], c = c[0]
    lstm_cell<E_DIM, 512><<<H_DIM, 512>>>(x_dev, hidden, c_in,
                                          w_ih_l0, w_hh_l0, b_ih_l0, b_hh_l0, h1_dev);

    // 3) LSTM layer 1: x = h1 (H=1024), h = hidden[1], c = c[1]
    lstm_cell<H_DIM, 256><<<H_DIM, 256>>>(h1_dev, hidden + H_DIM, c_in + H_DIM,
                                          w_ih_l1, w_hh_l1, b_ih_l1, b_hh_l1, h2_dev);

    // 4) FC head
    fc_kernel<<<C_CLS, 256>>>(fc_w, fc_b, out);
}

// round 3
// speedup vs baseline: 1.0786x; 1.0786x over previous
#include <cuda_runtime.h>
#include <math.h>

// Problem constants
#define S_LEN 16384
#define E_DIM 2048
#define H_DIM 1024
#define C_CLS 5
#define NCHUNK 256                        // colsum row chunks
#define ROWS_PER_CHUNK (S_LEN / NCHUNK)   // 64
#define COLSUM_BLOCKS (NCHUNK * 2)        // 512 (2 column halves of 256 float4)
#define HH_BLOCKS (4 * H_DIM / 8)         // 512 (8 gate-rows per 256-thr block)

// Scratch (device allocation forbidden -> __device__ globals)
__device__ float g_part[NCHUNK * E_DIM];  // 2 MB partial column sums
__device__ float g_x[E_DIM];              // attn_applied == column sum
__device__ float g_hh0[4 * H_DIM];        // w_hh_l0 @ h0 partial gates
__device__ float g_hh1[4 * H_DIM];        // w_hh_l1 @ hidden[1] partial gates
__device__ float g_h1[H_DIM];
__device__ float g_h2[H_DIM];

__device__ __forceinline__ float dot4(float4 a, float4 b) {
    return a.x * b.x + a.y * b.y + a.z * b.z + a.w * b.w;
}
__device__ __forceinline__ float sigf(float v) {
    return 1.0f / (1.0f + __expf(-v));
}
__device__ __forceinline__ float4 ldcs4(const float4* p) {
    return __ldcs(p);
}

// ---------------------------------------------------------------------------
// Phase 1 (fused, one launch): everything that depends only on raw inputs.
//   blocks [0, 512):      colsum partials of encoder_hiddens (134 MB)
//   blocks [512, 1024):   g_hh0 = w_hh_l0 @ hidden[0]        (16.8 MB)
//   blocks [1024, 1536):  g_hh1 = w_hh_l1 @ hidden[1]        (16.8 MB)
// All sections are pure streaming; together they keep DRAM saturated.
// ---------------------------------------------------------------------------
__global__ void __launch_bounds__(256) fused_phase1(const float* __restrict__ enc,
                                                    const float* __restrict__ hidden,
                                                    const float* __restrict__ w_hh_l0,
                                                    const float* __restrict__ w_hh_l1) {
    const int bid = blockIdx.x;
    const int tid = threadIdx.x;

    if (bid < COLSUM_BLOCKS) {
        // ---- column-sum partials ----
        const int chunk = bid >> 1;
        const int c4 = (bid & 1) * 256 + tid;       // float4 column [0, 512)
        const float4* __restrict__ e4 = (const float4*)enc;
        const size_t base = (size_t)chunk * ROWS_PER_CHUNK * (E_DIM / 4) + c4;
        float4 s = make_float4(0.f, 0.f, 0.f, 0.f);
#pragma unroll 8
        for (int r = 0; r < ROWS_PER_CHUNK; r++) {
            float4 v = ldcs4(&e4[base + (size_t)r * (E_DIM / 4)]);
            s.x += v.x; s.y += v.y; s.z += v.z; s.w += v.w;
        }
        ((float4*)g_part)[(size_t)chunk * (E_DIM / 4) + c4] = s;
    } else {
        // ---- hh GEMV partials: warp-per-gate-row ----
        const int sec = (bid < COLSUM_BLOCKS + HH_BLOCKS) ? 0 : 1;
        const int b = bid - COLSUM_BLOCKS - sec * HH_BLOCKS;
        const int warp = tid >> 5, lane = tid & 31;
        const int row = b * 8 + warp;               // [0, 4096)
        const float* __restrict__ w = sec ? w_hh_l1 : w_hh_l0;
        const float4* __restrict__ w4 = (const float4*)(w + (size_t)row * H_DIM);
        const float4* __restrict__ x4 = (const float4*)(hidden + sec * H_DIM);
        float s = 0.f;
#pragma unroll
        for (int i = 0; i < H_DIM / 128; i++) {     // 8 independent LDG.128 per lane
            float4 wv = ldcs4(&w4[i * 32 + lane]);
            float4 xv = x4[i * 32 + lane];
            s += dot4(wv, xv);
        }
#pragma unroll
        for (int o = 16; o; o >>= 1) s += __shfl_down_sync(0xffffffffu, s, o);
        if (lane == 0) (sec ? g_hh1 : g_hh0)[row] = s;
    }
}

// ---------------------------------------------------------------------------
// Phase 2: deterministic reduce of colsum partials -> g_x.
// ---------------------------------------------------------------------------
__global__ void __launch_bounds__(256) colsum_reduce() {
    const int e = blockIdx.x * blockDim.x + threadIdx.x;  // [0, 2048)
    float s = 0.f;
#pragma unroll 8
    for (int c = 0; c < NCHUNK; c++) s += g_part[c * E_DIM + e];
    g_x[e] = s;
}

// ---------------------------------------------------------------------------
// Phases 3/4: ih GEMV + gate combine, fused. One block (128 thr) per hidden
// unit j; warp g computes dot(w_ih[row g*H+j], x) with IN/128 fully unrolled
// independent LDG.128 per lane, then thread 0 adds the precomputed hh partial
// + biases and applies the LSTM nonlinearity.
// ---------------------------------------------------------------------------
template <int IN>
__global__ void __launch_bounds__(128) lstm_ih_combine(const float* __restrict__ xin,
                                                       const float* __restrict__ cprev,
                                                       const float* __restrict__ w_ih,
                                                       const float* __restrict__ b_ih,
                                                       const float* __restrict__ b_hh,
                                                       const float* __restrict__ hhpart,
                                                       float* __restrict__ hout) {
    const int j = blockIdx.x;
    const int warp = threadIdx.x >> 5, lane = threadIdx.x & 31;
    const float4* __restrict__ w4 = (const float4*)(w_ih + (size_t)(warp * H_DIM + j) * IN);
    const float4* __restrict__ x4 = (const float4*)xin;
    float s = 0.f;
#pragma unroll
    for (int i = 0; i < IN / 128; i++) {            // 16 (E) or 8 (H) indep loads/lane
        float4 wv = ldcs4(&w4[i * 32 + lane]);
        float4 xv = x4[i * 32 + lane];
        s += dot4(wv, xv);
    }
#pragma unroll
    for (int o = 16; o; o >>= 1) s += __shfl_down_sync(0xffffffffu, s, o);
    __shared__ float sg[4];
    if (lane == 0) sg[warp] = s;
    __syncthreads();
    if (threadIdx.x == 0) {
        float gi = sg[0] + hhpart[0 * H_DIM + j] + b_ih[0 * H_DIM + j] + b_hh[0 * H_DIM + j];
        float gf = sg[1] + hhpart[1 * H_DIM + j] + b_ih[1 * H_DIM + j] + b_hh[1 * H_DIM + j];
        float gg = sg[2] + hhpart[2 * H_DIM + j] + b_ih[2 * H_DIM + j] + b_hh[2 * H_DIM + j];
        float go = sg[3] + hhpart[3 * H_DIM + j] + b_ih[3 * H_DIM + j] + b_hh[3 * H_DIM + j];
        float c2 = sigf(gf) * cprev[j] + sigf(gi) * tanhf(gg);
        hout[j] = sigf(go) * tanhf(c2);
    }
}

// ---------------------------------------------------------------------------
// FC head: one block per class.
// ---------------------------------------------------------------------------
__global__ void __launch_bounds__(256) fc_kernel(const float* __restrict__ fc_w,
                                                 const float* __restrict__ fc_b,
                                                 float* __restrict__ out) {
    const int cls = blockIdx.x;
    const float4* __restrict__ h4 = (const float4*)g_h2;
    const float4* __restrict__ w4 = (const float4*)(fc_w + (size_t)cls * H_DIM);
    float s = 0.f;
    for (int t = threadIdx.x; t < H_DIM / 4; t += blockDim.x) s += dot4(w4[t], h4[t]);
#pragma unroll
    for (int o = 16; o; o >>= 1) s += __shfl_down_sync(0xffffffffu, s, o);
    __shared__ float sm[8];
    const int lane = threadIdx.x & 31, warp = threadIdx.x >> 5;
    if (lane == 0) sm[warp] = s;
    __syncthreads();
    if (threadIdx.x == 0) {
        float t = 0.f;
        const int nwarps = (int)(blockDim.x >> 5);
        for (int w = 0; w < nwarps; w++) t += sm[w];
        out[cls] = t + fc_b[cls];
    }
}

extern "C" void kernel_launch(void* const* d_in, const int* in_sizes, int n_in,
                              void* d_out, int out_size) {
    const float* enc     = (const float*)d_in[0];   // (S, 1, E)
    const float* hidden  = (const float*)d_in[1];   // (2, 1, H)
    const float* c_in    = (const float*)d_in[2];   // (2, 1, H)
    // d_in[3] attn_w, d_in[4] attn_b: dead — softmax over the size-1 output
    // axis is identically 1, so attn_applied is a plain column sum of enc.
    const float* w_ih_l0 = (const float*)d_in[5];
    const float* w_hh_l0 = (const float*)d_in[6];
    const float* b_ih_l0 = (const float*)d_in[7];
    const float* b_hh_l0 = (const float*)d_in[8];
    const float* w_ih_l1 = (const float*)d_in[9];
    const float* w_hh_l1 = (const float*)d_in[10];
    const float* b_ih_l1 = (const float*)d_in[11];
    const float* b_hh_l1 = (const float*)d_in[12];
    const float* fc_w    = (const float*)d_in[13];
    const float* fc_b    = (const float*)d_in[14];
    float* out = (float*)d_out;

    float* x_dev;   cudaGetSymbolAddress((void**)&x_dev,   g_x);
    float* hh0_dev; cudaGetSymbolAddress((void**)&hh0_dev, g_hh0);
    float* hh1_dev; cudaGetSymbolAddress((void**)&hh1_dev, g_hh1);
    float* h1_dev;  cudaGetSymbolAddress((void**)&h1_dev,  g_h1);
    float* h2_dev;  cudaGetSymbolAddress((void**)&h2_dev,  g_h2);

    // 1) colsum partials + BOTH hh GEMVs (all depend only on inputs) in one launch
    fused_phase1<<<COLSUM_BLOCKS + 2 * HH_BLOCKS, 256>>>(enc, hidden, w_hh_l0, w_hh_l1);

    // 2) reduce partials -> x (attn_applied)
    colsum_reduce<<<E_DIM / 256, 256>>>();

    // 3) LSTM layer 0: ih GEMV (x, E=2048) + combine with hh0 -> h1
    lstm_ih_combine<E_DIM><<<H_DIM, 128>>>(x_dev, c_in, w_ih_l0, b_ih_l0, b_hh_l0,
                                           hh0_dev, h1_dev);

    // 4) LSTM layer 1: ih GEMV (h1, H=1024) + combine with hh1 -> h2
    lstm_ih_combine<H_DIM><<<H_DIM, 128>>>(h1_dev, c_in + H_DIM, w_ih_l1, b_ih_l1, b_hh_l1,
                                           hh1_dev, h2_dev);

    // 5) FC head
    fc_kernel<<<C_CLS, 256>>>(fc_w, fc_b, out);
}